// round 8
// baseline (speedup 1.0000x reference)
#include <cuda_runtime.h>
#include <cuda_bf16.h>
#include <math.h>
#include <stdint.h>
#include <stddef.h>

// Problem constants
constexpr int B   = 2;
constexpr int T   = 768;
constexpr int KV  = 256;
constexpr int S   = 1024;
constexpr int D   = 1024;
constexpr int H   = 16;
constexpr int DH  = 64;
constexpr int L   = 6;
constexpr int V   = 32000;
constexpr int NTOK = B * S;
constexpr int PHYS_TOK = 5;

// ---------------- fp32 scratch ----------------------------------------------
__device__ float g_x  [NTOK * D];
__device__ float g_qkv[NTOK * 3 * D];
__device__ float g_o  [NTOK * D];
__device__ float g_ff [NTOK * 4 * D];
__device__ int   g_pe [B];

// ---------------- int8 double-word quantized storage -------------------------
__device__ char  wq1_qkv[L*3*D*D], wq0_qkv[L*3*D*D];
__device__ char  wq1_out[L*D*D],   wq0_out[L*D*D];
__device__ char  wq1_ff1[L*4*D*D], wq0_ff1[L*4*D*D];
__device__ char  wq1_ff2[L*4*D*D], wq0_ff2[L*4*D*D];
__device__ char  wq1_te [(size_t)V*D], wq0_te[(size_t)V*D];
__device__ float ws_qkv[L*3*D], ws_out[L*D], ws_ff1[L*4*D], ws_ff2[L*D], ws_te[V];
__device__ char  qa1[NTOK*4*D], qa0[NTOK*4*D];
__device__ float qsA[NTOK];

// ============================ PTX helpers ====================================
__device__ __forceinline__ uint32_t smem_to_u32(const void* p) {
    uint32_t a;
    asm("{ .reg .u64 t; cvta.to.shared.u64 t, %1; cvt.u32.u64 %0, t; }" : "=r"(a) : "l"(p));
    return a;
}
__device__ __forceinline__ void ldmx4(uint32_t* r, uint32_t addr) {
    asm volatile("ldmatrix.sync.aligned.m8n8.x4.shared.b16 {%0,%1,%2,%3}, [%4];"
        : "=r"(r[0]), "=r"(r[1]), "=r"(r[2]), "=r"(r[3]) : "r"(addr));
}
__device__ __forceinline__ void ldmx4t(uint32_t* r, uint32_t addr) {
    asm volatile("ldmatrix.sync.aligned.m8n8.x4.trans.shared.b16 {%0,%1,%2,%3}, [%4];"
        : "=r"(r[0]), "=r"(r[1]), "=r"(r[2]), "=r"(r[3]) : "r"(addr));
}
__device__ __forceinline__ void mma16816(float* c, const uint32_t* a, const uint32_t* b) {
    asm volatile("mma.sync.aligned.m16n8k16.row.col.f32.bf16.bf16.f32 "
        "{%0,%1,%2,%3}, {%4,%5,%6,%7}, {%8,%9}, {%0,%1,%2,%3};"
        : "+f"(c[0]), "+f"(c[1]), "+f"(c[2]), "+f"(c[3])
        : "r"(a[0]), "r"(a[1]), "r"(a[2]), "r"(a[3]), "r"(b[0]), "r"(b[1]));
}
__device__ __forceinline__ void mma16832(int* c, const uint32_t* a, const uint32_t* b) {
    asm volatile("mma.sync.aligned.m16n8k32.row.col.s32.s8.s8.s32 "
        "{%0,%1,%2,%3}, {%4,%5,%6,%7}, {%8,%9}, {%0,%1,%2,%3};"
        : "+r"(c[0]), "+r"(c[1]), "+r"(c[2]), "+r"(c[3])
        : "r"(a[0]), "r"(a[1]), "r"(a[2]), "r"(a[3]), "r"(b[0]), "r"(b[1]));
}
__device__ __forceinline__ void cp16(uint32_t dst, const void* src) {
    asm volatile("cp.async.cg.shared.global [%0], [%1], 16;" :: "r"(dst), "l"(src));
}
__device__ __forceinline__ void cp_commit() {
    asm volatile("cp.async.commit_group;" ::: "memory");
}
template<int N>
__device__ __forceinline__ void cp_wait() {
    asm volatile("cp.async.wait_group %0;" :: "n"(N) : "memory");
}
__device__ __forceinline__ uint32_t pack_bf2(float a, float b) {
    __nv_bfloat162 t;
    t.x = __float2bfloat16(a); t.y = __float2bfloat16(b);
    return *(uint32_t*)&t;
}

// ---------------- small kernels ----------------------------------------------
__global__ void pe_kernel(const int* __restrict__ idx) {
    int b = threadIdx.x;
    if (b < B) {
        int pe = 0;
        for (int s = 0; s < T; s++)
            if (idx[b * T + s] == PHYS_TOK) { pe = s + 1; break; }
        g_pe[b] = pe;
    }
}

__global__ void embed_kernel(const int* __restrict__ idx, const float* __restrict__ vis,
                             const float* __restrict__ wte, const float* __restrict__ wpe) {
    int i = blockIdx.x * blockDim.x + threadIdx.x;
    int d = i & (D - 1);
    int p = (i / D) & (S - 1);
    int b = i / (D * S);
    int pe = g_pe[b];
    float v;
    if (p >= pe && p < pe + KV) {
        v = vis[((size_t)b * KV + (p - pe)) * D + d];
    } else {
        int ti = (p < pe) ? p : (p - KV);
        ti = min(max(ti, 0), T - 1);
        v = wte[(size_t)idx[b * T + ti] * D + d];
    }
    g_x[i] = v + wpe[(size_t)p * D + d];
}

__device__ __forceinline__ void quant_one(float y, float invS, char* q1, char* q0) {
    int a15 = __float2int_rn(y * invS);
    a15 = min(max(a15, -32639), 32639);
    int hi = (a15 + 128) >> 8;
    *q1 = (char)hi;
    *q0 = (char)(a15 - (hi << 8));
}

// weight quantization: one warp per row (vectorized by 4)
__global__ void wquant_kernel(const float* __restrict__ W, char* __restrict__ w1,
                              char* __restrict__ w0, float* __restrict__ sW,
                              int rows, int K) {
    int warp = (blockIdx.x * blockDim.x + threadIdx.x) >> 5;
    int lane = threadIdx.x & 31;
    if (warp >= rows) return;
    const float* row = W + (size_t)warp * K;
    float m = 0.f;
    for (int j = lane * 4; j < K; j += 128) {
        float4 v = *(const float4*)(row + j);
        m = fmaxf(m, fmaxf(fmaxf(fabsf(v.x), fabsf(v.y)), fmaxf(fabsf(v.z), fabsf(v.w))));
    }
#pragma unroll
    for (int o = 16; o; o >>= 1) m = fmaxf(m, __shfl_xor_sync(~0u, m, o));
    float invS = (m > 0.f) ? 32639.f / m : 0.f;
    if (lane == 0) sW[warp] = m * (1.f / 32639.f);
    for (int j = lane * 4; j < K; j += 128) {
        float4 v = *(const float4*)(row + j);
        char c1[4], c0[4];
        quant_one(v.x, invS, c1 + 0, c0 + 0);
        quant_one(v.y, invS, c1 + 1, c0 + 1);
        quant_one(v.z, invS, c1 + 2, c0 + 2);
        quant_one(v.w, invS, c1 + 3, c0 + 3);
        *(char4*)(w1 + (size_t)warp * K + j) = *(char4*)c1;
        *(char4*)(w0 + (size_t)warp * K + j) = *(char4*)c0;
    }
}

// LayerNorm + int8 double-word quantization (row-local)
__global__ void ln_quant_kernel(const float* __restrict__ in,
                                const float* __restrict__ w, const float* __restrict__ b,
                                char* __restrict__ q1, char* __restrict__ q0,
                                float* __restrict__ sA) {
    int row = blockIdx.x;
    const float* x = in + (size_t)row * D;
    float v[4]; float s = 0.f, s2 = 0.f;
#pragma unroll
    for (int u = 0; u < 4; u++) { v[u] = x[threadIdx.x + u * 256]; s += v[u]; s2 += v[u] * v[u]; }
#pragma unroll
    for (int o = 16; o; o >>= 1) { s += __shfl_xor_sync(~0u, s, o); s2 += __shfl_xor_sync(~0u, s2, o); }
    __shared__ float sh1[8], sh2[8];
    int wid = threadIdx.x >> 5, lid = threadIdx.x & 31;
    if (lid == 0) { sh1[wid] = s; sh2[wid] = s2; }
    __syncthreads();
    s = 0.f; s2 = 0.f;
#pragma unroll
    for (int wg = 0; wg < 8; wg++) { s += sh1[wg]; s2 += sh2[wg]; }
    float mean = s * (1.f / D);
    float var  = s2 * (1.f / D) - mean * mean;
    float inv  = rsqrtf(var + 1e-5f);
    float y[4], mx = 0.f;
#pragma unroll
    for (int u = 0; u < 4; u++) {
        int j = threadIdx.x + u * 256;
        y[u] = (v[u] - mean) * inv * w[j] + b[j];
        mx = fmaxf(mx, fabsf(y[u]));
    }
#pragma unroll
    for (int o = 16; o; o >>= 1) mx = fmaxf(mx, __shfl_xor_sync(~0u, mx, o));
    __syncthreads();
    if (lid == 0) sh1[wid] = mx;
    __syncthreads();
    mx = sh1[0];
#pragma unroll
    for (int wg = 1; wg < 8; wg++) mx = fmaxf(mx, sh1[wg]);
    float invS = (mx > 0.f) ? 32639.f / mx : 0.f;
    if (threadIdx.x == 0) sA[row] = mx * (1.f / 32639.f);
#pragma unroll
    for (int u = 0; u < 4; u++) {
        int j = threadIdx.x + u * 256;
        char c1, c0;
        quant_one(y[u], invS, &c1, &c0);
        q1[(size_t)row * D + j] = c1;
        q0[(size_t)row * D + j] = c0;
    }
}

// generic activation row quantization (block per row)
__global__ void act_quant_kernel(const float* __restrict__ X, char* __restrict__ q1,
                                 char* __restrict__ q0, float* __restrict__ sA, int K) {
    int row = blockIdx.x;
    const float* x = X + (size_t)row * K;
    float m = 0.f;
    for (int j = threadIdx.x; j < K; j += 256) m = fmaxf(m, fabsf(x[j]));
#pragma unroll
    for (int o = 16; o; o >>= 1) m = fmaxf(m, __shfl_xor_sync(~0u, m, o));
    __shared__ float sh[8];
    int wid = threadIdx.x >> 5, lid = threadIdx.x & 31;
    if (lid == 0) sh[wid] = m;
    __syncthreads();
    m = sh[0];
#pragma unroll
    for (int wg = 1; wg < 8; wg++) m = fmaxf(m, sh[wg]);
    float invS = (m > 0.f) ? 32639.f / m : 0.f;
    if (threadIdx.x == 0) sA[row] = m * (1.f / 32639.f);
    for (int j = threadIdx.x; j < K; j += 256) {
        char c1, c0;
        quant_one(x[j], invS, &c1, &c0);
        q1[(size_t)row * K + j] = c1;
        q0[(size_t)row * K + j] = c0;
    }
}

__device__ __forceinline__ float gelu_exact(float x) {
    return 0.5f * x * (1.f + erff(x * 0.70710678118654752f));
}

// ================= int8 double-word GEMM (IMMA m16n8k32) =====================
// C[M,N] = (sA.(A1*256+A0)) @ (sW.(W1*256+W0))^T, drop A0W0 term.
// 128x128 CTA tile, BK=64 (s8), 256 threads (8 warps 4x2), warp tile 32x64.
constexpr int LDSROW = 40;                    // b16 units per row (32 data + 8 pad)
constexpr int TILE_BYTES = 128 * LDSROW * 2;  // 10240 (128 rows x 80B)
constexpr int BUF_BYTES  = 4 * TILE_BYTES;    // 40960 (A1,A0,W1,W0)
constexpr int GEMM_SMEM  = 2 * BUF_BYTES;     // 81920

__device__ __forceinline__ void cp_tile8(uint32_t dst, const char* __restrict__ src,
                                         int Kd, int k0) {
    int tid = threadIdx.x;
#pragma unroll
    for (int i = 0; i < 2; i++) {
        int v = tid * 2 + i;
        int row = v >> 2, seg = v & 3;
        cp16(dst + (uint32_t)(row * 80 + seg * 16),
             src + (size_t)row * Kd + k0 + seg * 16);
    }
}

template<bool BIAS, bool GELU, bool RES>
__global__ __launch_bounds__(256, 1)
void gemm_i8(const char* __restrict__ A1, const char* __restrict__ A0,
             const float* __restrict__ sA,
             const char* __restrict__ W1, const char* __restrict__ W0,
             const float* __restrict__ sW,
             const float* __restrict__ bias, const float* __restrict__ res,
             float* __restrict__ C, int N, int Kd) {
    extern __shared__ char smem[];
    const uint32_t sbase = smem_to_u32(smem);

    const int tid  = threadIdx.x;
    const int lane = tid & 31;
    const int wid  = tid >> 5;
    const int wm   = wid >> 1;
    const int wn   = wid & 1;
    const int bm   = blockIdx.x * 128;
    const int bn   = blockIdx.y * 128;

    const char* pA1 = A1 + (size_t)bm * Kd;
    const char* pA0 = A0 + (size_t)bm * Kd;
    const char* pW1 = W1 + (size_t)bn * Kd;
    const char* pW0 = W0 + (size_t)bn * Kd;

    const uint32_t frag_lane = (uint32_t)((lane & 15) * LDSROW + (lane >> 4) * 8);
    const int nch = Kd / 64;

    auto issue = [&](int ch) {
        uint32_t b = sbase + (uint32_t)(ch & 1) * BUF_BYTES;
        int k0 = ch * 64;
        cp_tile8(b,                  pA1, Kd, k0);
        cp_tile8(b + TILE_BYTES,     pA0, Kd, k0);
        cp_tile8(b + 2 * TILE_BYTES, pW1, Kd, k0);
        cp_tile8(b + 3 * TILE_BYTES, pW0, Kd, k0);
        cp_commit();
    };

    int acc1[2][8][4], acc2[2][8][4];
#pragma unroll
    for (int mt = 0; mt < 2; mt++)
#pragma unroll
        for (int nt = 0; nt < 8; nt++)
#pragma unroll
            for (int q = 0; q < 4; q++) { acc1[mt][nt][q] = 0; acc2[mt][nt][q] = 0; }

    issue(0);
    if (nch > 1) issue(1);

    for (int ch = 0; ch < nch; ch++) {
        if (ch < nch - 1) cp_wait<1>(); else cp_wait<0>();
        __syncthreads();
        uint32_t b = sbase + (uint32_t)(ch & 1) * BUF_BYTES;
#pragma unroll
        for (int ks = 0; ks < 2; ks++) {
            uint32_t a1f[2][4], a0f[2][4];
#pragma unroll
            for (int mt = 0; mt < 2; mt++) {
                uint32_t off = ((uint32_t)((wm * 32 + mt * 16) * LDSROW + ks * 16) + frag_lane) * 2;
                ldmx4(a1f[mt], b + off);
                ldmx4(a0f[mt], b + TILE_BYTES + off);
            }
            uint32_t bw1[8][2], bw0[8][2];
#pragma unroll
            for (int jj = 0; jj < 4; jj++) {
                uint32_t off = ((uint32_t)((wn * 64 + jj * 16) * LDSROW + ks * 16) + frag_lane) * 2;
                uint32_t t1[4], t0[4];
                ldmx4(t1, b + 2 * TILE_BYTES + off);
                ldmx4(t0, b + 3 * TILE_BYTES + off);
                bw1[jj * 2][0]     = t1[0]; bw1[jj * 2 + 1][0] = t1[1];
                bw1[jj * 2][1]     = t1[2]; bw1[jj * 2 + 1][1] = t1[3];
                bw0[jj * 2][0]     = t0[0]; bw0[jj * 2 + 1][0] = t0[1];
                bw0[jj * 2][1]     = t0[2]; bw0[jj * 2 + 1][1] = t0[3];
            }
            // 3 passes (long reuse distance per accumulator)
#pragma unroll
            for (int mt = 0; mt < 2; mt++)
#pragma unroll
                for (int nt = 0; nt < 8; nt++)
                    mma16832(acc1[mt][nt], a1f[mt], bw1[nt]);
#pragma unroll
            for (int mt = 0; mt < 2; mt++)
#pragma unroll
                for (int nt = 0; nt < 8; nt++)
                    mma16832(acc2[mt][nt], a1f[mt], bw0[nt]);
#pragma unroll
            for (int mt = 0; mt < 2; mt++)
#pragma unroll
                for (int nt = 0; nt < 8; nt++)
                    mma16832(acc2[mt][nt], a0f[mt], bw1[nt]);
        }
        __syncthreads();
        if (ch + 2 < nch) issue(ch + 2);
    }

    // epilogue: m16n8 frag: e0,e1 -> (row=l>>2, col=(l&3)*2+{0,1}); e2,e3 -> row+8
    const int row0 = bm + wm * 32;
    const int col0 = bn + wn * 64;
#pragma unroll
    for (int mt = 0; mt < 2; mt++) {
        int rbase = row0 + mt * 16 + (lane >> 2);
        float sr0 = sA[rbase], sr1 = sA[rbase + 8];
#pragma unroll
        for (int nt = 0; nt < 8; nt++) {
            int cl = col0 + nt * 8 + (lane & 3) * 2;
            float sc0 = sW[cl], sc1 = sW[cl + 1];
#pragma unroll
            for (int half = 0; half < 2; half++) {
                int rr = rbase + half * 8;
                float sr = half ? sr1 : sr0;
                float v0 = fmaf(65536.f, (float)acc1[mt][nt][half * 2],
                                256.f * (float)acc2[mt][nt][half * 2]) * (sr * sc0);
                float v1 = fmaf(65536.f, (float)acc1[mt][nt][half * 2 + 1],
                                256.f * (float)acc2[mt][nt][half * 2 + 1]) * (sr * sc1);
                if (BIAS) { v0 += bias[cl]; v1 += bias[cl + 1]; }
                if (GELU) { v0 = gelu_exact(v0); v1 = gelu_exact(v1); }
                if (RES) {
                    const float* rp = res + (size_t)rr * N + cl;
                    v0 += rp[0]; v1 += rp[1];
                }
                *(float2*)(C + (size_t)rr * N + cl) = make_float2(v0, v1);
            }
        }
    }
}

// ================= fused flash attention (split-bf16 mma) ====================
// grid (S/128, B*H), 256 threads (8 warps x 16 q-rows). K-tile = 64 keys.
constexpr int QROW = 72;   // 64 + 8 pad
constexpr int FLASH_SMEM = (128 * QROW * 2 + 4 * 64 * QROW) * 2; // Qh,Ql + Kh,Kl,Vh,Vl

__global__ __launch_bounds__(256, 1)
void flash_kernel(const float* __restrict__ qkv, float* __restrict__ out) {
    extern __shared__ char smem[];
    __nv_bfloat16* sQh = (__nv_bfloat16*)smem;
    __nv_bfloat16* sQl = sQh + 128 * QROW;
    __nv_bfloat16* sKh = sQl + 128 * QROW;
    __nv_bfloat16* sKl = sKh + 64 * QROW;
    __nv_bfloat16* sVh = sKl + 64 * QROW;
    __nv_bfloat16* sVl = sVh + 64 * QROW;

    const int tid = threadIdx.x, lane = tid & 31, w = tid >> 5;
    const int bh = blockIdx.y, b = bh >> 4, h = bh & 15;
    const int qBase = blockIdx.x * 128;
    const int pe = g_pe[b], ve = pe + KV;

    for (int i = tid; i < 2048; i += 256) {
        int row = i >> 4, col = (i & 15) * 4;
        float4 q4 = *(const float4*)(qkv + (size_t)(b * S + qBase + row) * (3 * D) + h * DH + col);
        int o = row * QROW + col;
        float f[4] = { q4.x, q4.y, q4.z, q4.w };
#pragma unroll
        for (int u = 0; u < 4; u++) {
            __nv_bfloat16 hh = __float2bfloat16(f[u]);
            sQh[o + u] = hh;
            sQl[o + u] = __float2bfloat16(f[u] - __bfloat162float(hh));
        }
    }
    __syncthreads();

    const uint32_t aQh = smem_to_u32(sQh), aQl = smem_to_u32(sQl);
    const uint32_t aKh = smem_to_u32(sKh), aKl = smem_to_u32(sKl);
    const uint32_t aVh = smem_to_u32(sVh), aVl = smem_to_u32(sVl);
    const uint32_t flq = (uint32_t)((lane & 15) * QROW + (lane >> 4) * 8);
    uint32_t qh[4][4], ql[4][4];
#pragma unroll
    for (int kk = 0; kk < 4; kk++) {
        uint32_t off = ((uint32_t)(w * 16 * QROW + kk * 16) + flq) * 2;
        ldmx4(qh[kk], aQh + off);
        ldmx4(ql[kk], aQl + off);
    }

    float acc[8][4];
#pragma unroll
    for (int nt = 0; nt < 8; nt++)
#pragma unroll
        for (int e = 0; e < 4; e++) acc[nt][e] = 0.f;
    float m0 = -1e30f, m1 = -1e30f, l0 = 0.f, l1 = 0.f;

    const int qr = qBase + w * 16 + (lane >> 2);
    const int kEnd = min(S, max(qBase + 128, ve));

    for (int k0 = 0; k0 < kEnd; k0 += 64) {
        __syncthreads();
        for (int i = tid; i < 1024; i += 256) {
            int row = i >> 4, col = (i & 15) * 4;
            const float* base = qkv + (size_t)(b * S + k0 + row) * (3 * D) + h * DH + col;
            float4 k4 = *(const float4*)(base + D);
            float4 v4 = *(const float4*)(base + 2 * D);
            int o = row * QROW + col;
            float fk[4] = { k4.x, k4.y, k4.z, k4.w };
            float fv[4] = { v4.x, v4.y, v4.z, v4.w };
#pragma unroll
            for (int u = 0; u < 4; u++) {
                __nv_bfloat16 hk = __float2bfloat16(fk[u]);
                sKh[o + u] = hk;
                sKl[o + u] = __float2bfloat16(fk[u] - __bfloat162float(hk));
                __nv_bfloat16 hv = __float2bfloat16(fv[u]);
                sVh[o + u] = hv;
                sVl[o + u] = __float2bfloat16(fv[u] - __bfloat162float(hv));
            }
        }
        __syncthreads();

        float c[8][4];
#pragma unroll
        for (int nt = 0; nt < 8; nt++)
#pragma unroll
            for (int e = 0; e < 4; e++) c[nt][e] = 0.f;
#pragma unroll
        for (int kk = 0; kk < 4; kk++) {
#pragma unroll
            for (int jj = 0; jj < 4; jj++) {
                uint32_t off = ((uint32_t)((jj * 16) * QROW + kk * 16) + flq) * 2;
                uint32_t th[4], tl[4];
                ldmx4(th, aKh + off);
                ldmx4(tl, aKl + off);
                uint32_t bh0[2] = { th[0], th[2] }, bh1[2] = { th[1], th[3] };
                uint32_t bl0[2] = { tl[0], tl[2] }, bl1[2] = { tl[1], tl[3] };
                mma16816(c[jj * 2],     qh[kk], bh0);
                mma16816(c[jj * 2],     qh[kk], bl0);
                mma16816(c[jj * 2],     ql[kk], bh0);
                mma16816(c[jj * 2 + 1], qh[kk], bh1);
                mma16816(c[jj * 2 + 1], qh[kk], bl1);
                mma16816(c[jj * 2 + 1], ql[kk], bh1);
            }
        }

        float mx0 = -1e30f, mx1 = -1e30f;
#pragma unroll
        for (int nt = 0; nt < 8; nt++) {
            int kc = k0 + nt * 8 + (lane & 3) * 2;
#pragma unroll
            for (int e = 0; e < 4; e++) {
                int q = qr + ((e >= 2) ? 8 : 0);
                int k = kc + (e & 1);
                bool allowed = (q < pe && k < pe) ||
                               (q >= pe && q < ve && k < ve) ||
                               (q >= ve && k <= q);
                float s = allowed ? c[nt][e] * 0.125f : -1e9f;
                c[nt][e] = s;
                if (e < 2) mx0 = fmaxf(mx0, s); else mx1 = fmaxf(mx1, s);
            }
        }
        mx0 = fmaxf(mx0, __shfl_xor_sync(~0u, mx0, 1));
        mx0 = fmaxf(mx0, __shfl_xor_sync(~0u, mx0, 2));
        mx1 = fmaxf(mx1, __shfl_xor_sync(~0u, mx1, 1));
        mx1 = fmaxf(mx1, __shfl_xor_sync(~0u, mx1, 2));

        float mn0 = fmaxf(m0, mx0), mn1 = fmaxf(m1, mx1);
        float al0 = __expf(m0 - mn0), al1 = __expf(m1 - mn1);
        m0 = mn0; m1 = mn1;

        uint32_t ph[4][4], pl[4][4];
        float rs0 = 0.f, rs1 = 0.f;
#pragma unroll
        for (int nt = 0; nt < 8; nt++) {
            float p0 = __expf(c[nt][0] - m0);
            float p1 = __expf(c[nt][1] - m0);
            float p2 = __expf(c[nt][2] - m1);
            float p3 = __expf(c[nt][3] - m1);
            rs0 += p0 + p1; rs1 += p2 + p3;
            __nv_bfloat16 h0 = __float2bfloat16(p0), h1 = __float2bfloat16(p1);
            __nv_bfloat16 h2 = __float2bfloat16(p2), h3 = __float2bfloat16(p3);
            int ck = nt >> 1, ps = (nt & 1) * 2;
            __nv_bfloat162 t;
            t.x = h0; t.y = h1; ph[ck][ps]     = *(uint32_t*)&t;
            t.x = h2; t.y = h3; ph[ck][ps + 1] = *(uint32_t*)&t;
            pl[ck][ps]     = pack_bf2(p0 - __bfloat162float(h0), p1 - __bfloat162float(h1));
            pl[ck][ps + 1] = pack_bf2(p2 - __bfloat162float(h2), p3 - __bfloat162float(h3));
        }
        rs0 += __shfl_xor_sync(~0u, rs0, 1); rs0 += __shfl_xor_sync(~0u, rs0, 2);
        rs1 += __shfl_xor_sync(~0u, rs1, 1); rs1 += __shfl_xor_sync(~0u, rs1, 2);
        l0 = l0 * al0 + rs0;
        l1 = l1 * al1 + rs1;

#pragma unroll
        for (int nt = 0; nt < 8; nt++) {
            acc[nt][0] *= al0; acc[nt][1] *= al0;
            acc[nt][2] *= al1; acc[nt][3] *= al1;
        }

        const uint32_t flv = (uint32_t)(((lane & 7) + ((lane >> 3) & 1) * 8) * QROW + (lane >> 4) * 8);
#pragma unroll
        for (int kk = 0; kk < 4; kk++) {
#pragma unroll
            for (int jj = 0; jj < 4; jj++) {
                uint32_t off = ((uint32_t)(kk * 16 * QROW + jj * 16) + flv) * 2;
                uint32_t th[4], tl[4];
                ldmx4t(th, aVh + off);
                ldmx4t(tl, aVl + off);
                uint32_t bh0[2] = { th[0], th[1] }, bh1[2] = { th[2], th[3] };
                uint32_t bl0[2] = { tl[0], tl[1] }, bl1[2] = { tl[2], tl[3] };
                mma16816(acc[jj * 2],     ph[kk], bh0);
                mma16816(acc[jj * 2],     ph[kk], bl0);
                mma16816(acc[jj * 2],     pl[kk], bh0);
                mma16816(acc[jj * 2 + 1], ph[kk], bh1);
                mma16816(acc[jj * 2 + 1], ph[kk], bl1);
                mma16816(acc[jj * 2 + 1], pl[kk], bh1);
            }
        }
    }

    const float il0 = 1.f / l0, il1 = 1.f / l1;
#pragma unroll
    for (int nt = 0; nt < 8; nt++) {
        int dcol = h * DH + nt * 8 + (lane & 3) * 2;
        size_t o0 = (size_t)(b * S + qr) * D + dcol;
        size_t o1 = (size_t)(b * S + qr + 8) * D + dcol;
        *(float2*)(out + o0) = make_float2(acc[nt][0] * il0, acc[nt][1] * il0);
        *(float2*)(out + o1) = make_float2(acc[nt][2] * il1, acc[nt][3] * il1);
    }
}

// ---------------- host: launch sequence --------------------------------------
static inline void wq(const float* W, char* w1, char* w0, float* sW, int rows, int K) {
    wquant_kernel<<<(rows + 7) / 8, 256>>>(W, w1, w0, sW, rows, K);
}

extern "C" void kernel_launch(void* const* d_in, const int* in_sizes, int n_in,
                              void* d_out, int out_size) {
    const int*   idx    = (const int*)  d_in[0];
    const float* vis    = (const float*)d_in[1];
    const float* wte    = (const float*)d_in[2];
    const float* wpe    = (const float*)d_in[3];
    const float* qkv_w  = (const float*)d_in[4];
    const float* qkv_b  = (const float*)d_in[5];
    const float* out_w  = (const float*)d_in[6];
    const float* out_b  = (const float*)d_in[7];
    const float* ln1_w  = (const float*)d_in[8];
    const float* ln1_b  = (const float*)d_in[9];
    const float* ln2_w  = (const float*)d_in[10];
    const float* ln2_b  = (const float*)d_in[11];
    const float* ff1_w  = (const float*)d_in[12];
    const float* ff1_b  = (const float*)d_in[13];
    const float* ff2_w  = (const float*)d_in[14];
    const float* ff2_b  = (const float*)d_in[15];
    const float* lnf_w  = (const float*)d_in[16];
    const float* lnf_b  = (const float*)d_in[17];
    float* logits = (float*)d_out;

    cudaFuncSetAttribute(gemm_i8<true,  false, false>, cudaFuncAttributeMaxDynamicSharedMemorySize, GEMM_SMEM);
    cudaFuncSetAttribute(gemm_i8<true,  false, true >, cudaFuncAttributeMaxDynamicSharedMemorySize, GEMM_SMEM);
    cudaFuncSetAttribute(gemm_i8<true,  true,  false>, cudaFuncAttributeMaxDynamicSharedMemorySize, GEMM_SMEM);
    cudaFuncSetAttribute(gemm_i8<false, false, false>, cudaFuncAttributeMaxDynamicSharedMemorySize, GEMM_SMEM);
    cudaFuncSetAttribute(flash_kernel, cudaFuncAttributeMaxDynamicSharedMemorySize, FLASH_SMEM);

    float *px, *pqkv, *po, *pff;
    cudaGetSymbolAddress((void**)&px,   g_x);
    cudaGetSymbolAddress((void**)&pqkv, g_qkv);
    cudaGetSymbolAddress((void**)&po,   g_o);
    cudaGetSymbolAddress((void**)&pff,  g_ff);
    char *pa1, *pa0, *q1qkv, *q0qkv, *q1out, *q0out, *q1f1, *q0f1, *q1f2, *q0f2, *q1te, *q0te;
    float *psA, *sqkv, *sout, *sf1, *sf2, *ste;
    cudaGetSymbolAddress((void**)&pa1,  qa1);
    cudaGetSymbolAddress((void**)&pa0,  qa0);
    cudaGetSymbolAddress((void**)&psA,  qsA);
    cudaGetSymbolAddress((void**)&q1qkv, wq1_qkv); cudaGetSymbolAddress((void**)&q0qkv, wq0_qkv);
    cudaGetSymbolAddress((void**)&q1out, wq1_out); cudaGetSymbolAddress((void**)&q0out, wq0_out);
    cudaGetSymbolAddress((void**)&q1f1,  wq1_ff1); cudaGetSymbolAddress((void**)&q0f1,  wq0_ff1);
    cudaGetSymbolAddress((void**)&q1f2,  wq1_ff2); cudaGetSymbolAddress((void**)&q0f2,  wq0_ff2);
    cudaGetSymbolAddress((void**)&q1te,  wq1_te);  cudaGetSymbolAddress((void**)&q0te,  wq0_te);
    cudaGetSymbolAddress((void**)&sqkv, ws_qkv);
    cudaGetSymbolAddress((void**)&sout, ws_out);
    cudaGetSymbolAddress((void**)&sf1,  ws_ff1);
    cudaGetSymbolAddress((void**)&sf2,  ws_ff2);
    cudaGetSymbolAddress((void**)&ste,  ws_te);

    // weight quantization (must run every call — determinism)
    wq(qkv_w, q1qkv, q0qkv, sqkv, L * 3 * D, D);
    wq(out_w, q1out, q0out, sout, L * D, D);
    wq(ff1_w, q1f1,  q0f1,  sf1,  L * 4 * D, D);
    wq(ff2_w, q1f2,  q0f2,  sf2,  L * D, 4 * D);
    wq(wte,   q1te,  q0te,  ste,  V, D);

    pe_kernel<<<1, 32>>>(idx);
    embed_kernel<<<(NTOK * D) / 256, 256>>>(idx, vis, wte, wpe);

    for (int l = 0; l < L; l++) {
        const char* lw1q = q1qkv + (size_t)l * 3 * D * D;
        const char* lw0q = q0qkv + (size_t)l * 3 * D * D;
        const char* lw1o = q1out + (size_t)l * D * D;
        const char* lw0o = q0out + (size_t)l * D * D;
        const char* lw1f1 = q1f1 + (size_t)l * 4 * D * D;
        const char* lw0f1 = q0f1 + (size_t)l * 4 * D * D;
        const char* lw1f2 = q1f2 + (size_t)l * 4 * D * D;
        const char* lw0f2 = q0f2 + (size_t)l * 4 * D * D;
        const float* qb  = qkv_b + (size_t)l * 3 * D;
        const float* ob  = out_b + (size_t)l * D;
        const float* f1b = ff1_b + (size_t)l * 4 * D;
        const float* f2b = ff2_b + (size_t)l * D;

        ln_quant_kernel<<<NTOK, 256>>>(px, ln1_w + l * D, ln1_b + l * D, pa1, pa0, psA);
        gemm_i8<true, false, false><<<dim3(NTOK / 128, 3 * D / 128), 256, GEMM_SMEM>>>(
            pa1, pa0, psA, lw1q, lw0q, sqkv + (size_t)l * 3 * D, qb, nullptr, pqkv, 3 * D, D);

        flash_kernel<<<dim3(S / 128, B * H), 256, FLASH_SMEM>>>(pqkv, po);
        act_quant_kernel<<<NTOK, 256>>>(po, pa1, pa0, psA, D);

        gemm_i8<true, false, true><<<dim3(NTOK / 128, D / 128), 256, GEMM_SMEM>>>(
            pa1, pa0, psA, lw1o, lw0o, sout + (size_t)l * D, ob, px, px, D, D);

        ln_quant_kernel<<<NTOK, 256>>>(px, ln2_w + l * D, ln2_b + l * D, pa1, pa0, psA);
        gemm_i8<true, true, false><<<dim3(NTOK / 128, 4 * D / 128), 256, GEMM_SMEM>>>(
            pa1, pa0, psA, lw1f1, lw0f1, sf1 + (size_t)l * 4 * D, f1b, nullptr, pff, 4 * D, D);

        act_quant_kernel<<<NTOK, 256>>>(pff, pa1, pa0, psA, 4 * D);
        gemm_i8<true, false, true><<<dim3(NTOK / 128, D / 128), 256, GEMM_SMEM>>>(
            pa1, pa0, psA, lw1f2, lw0f2, sf2 + (size_t)l * D, f2b, px, px, D, 4 * D);
    }

    ln_quant_kernel<<<NTOK, 256>>>(px, lnf_w, lnf_b, pa1, pa0, psA);
    gemm_i8<false, false, false><<<dim3(NTOK / 128, V / 128), 256, GEMM_SMEM>>>(
        pa1, pa0, psA, q1te, q0te, ste, nullptr, nullptr, logits, V, D);
}

// round 9
// speedup vs baseline: 2.5608x; 2.5608x over previous
#include <cuda_runtime.h>
#include <cuda_bf16.h>
#include <cuda_fp16.h>
#include <math.h>
#include <stdint.h>
#include <stddef.h>

// Problem constants
constexpr int B   = 2;
constexpr int T   = 768;
constexpr int KV  = 256;
constexpr int S   = 1024;
constexpr int D   = 1024;
constexpr int H   = 16;
constexpr int DH  = 64;
constexpr int L   = 6;
constexpr int V   = 32000;
constexpr int NTOK = B * S;
constexpr int PHYS_TOK = 5;

// ---------------- fp32 scratch ----------------------------------------------
__device__ float g_x  [NTOK * D];
__device__ float g_qkv[NTOK * 3 * D];
__device__ int   g_pe [B];

// ---------------- fp16 storage: weights single, activations split hi/lo ------
__device__ __half w_qkv[L*3*D*D];
__device__ __half w_out[L*D*D];
__device__ __half w_ff1[L*4*D*D];
__device__ __half w_ff2[L*4*D*D];
__device__ __half w_te [(size_t)V*D];
__device__ __half a_h [NTOK*D],   a_l [NTOK*D];     // activations [NTOK,D]
__device__ __half a2_h[NTOK*4*D], a2_l[NTOK*4*D];   // FF hidden   [NTOK,4D]

// ============================ PTX helpers ====================================
__device__ __forceinline__ uint32_t smem_to_u32(const void* p) {
    uint32_t a;
    asm("{ .reg .u64 t; cvta.to.shared.u64 t, %1; cvt.u32.u64 %0, t; }" : "=r"(a) : "l"(p));
    return a;
}
__device__ __forceinline__ void ldmx4(uint32_t* r, uint32_t addr) {
    asm volatile("ldmatrix.sync.aligned.m8n8.x4.shared.b16 {%0,%1,%2,%3}, [%4];"
        : "=r"(r[0]), "=r"(r[1]), "=r"(r[2]), "=r"(r[3]) : "r"(addr));
}
__device__ __forceinline__ void ldmx4t(uint32_t* r, uint32_t addr) {
    asm volatile("ldmatrix.sync.aligned.m8n8.x4.trans.shared.b16 {%0,%1,%2,%3}, [%4];"
        : "=r"(r[0]), "=r"(r[1]), "=r"(r[2]), "=r"(r[3]) : "r"(addr));
}
// bf16 mma (flash attention)
__device__ __forceinline__ void mma_bf16(float* c, const uint32_t* a, const uint32_t* b) {
    asm volatile("mma.sync.aligned.m16n8k16.row.col.f32.bf16.bf16.f32 "
        "{%0,%1,%2,%3}, {%4,%5,%6,%7}, {%8,%9}, {%0,%1,%2,%3};"
        : "+f"(c[0]), "+f"(c[1]), "+f"(c[2]), "+f"(c[3])
        : "r"(a[0]), "r"(a[1]), "r"(a[2]), "r"(a[3]), "r"(b[0]), "r"(b[1]));
}
// fp16 mma (GEMMs)
__device__ __forceinline__ void mma_fp16(float* c, const uint32_t* a, const uint32_t* b) {
    asm volatile("mma.sync.aligned.m16n8k16.row.col.f32.f16.f16.f32 "
        "{%0,%1,%2,%3}, {%4,%5,%6,%7}, {%8,%9}, {%0,%1,%2,%3};"
        : "+f"(c[0]), "+f"(c[1]), "+f"(c[2]), "+f"(c[3])
        : "r"(a[0]), "r"(a[1]), "r"(a[2]), "r"(a[3]), "r"(b[0]), "r"(b[1]));
}
__device__ __forceinline__ void cp16(uint32_t dst, const void* src) {
    asm volatile("cp.async.cg.shared.global [%0], [%1], 16;" :: "r"(dst), "l"(src));
}
__device__ __forceinline__ void cp_commit() {
    asm volatile("cp.async.commit_group;" ::: "memory");
}
template<int N>
__device__ __forceinline__ void cp_wait() {
    asm volatile("cp.async.wait_group %0;" :: "n"(N) : "memory");
}
__device__ __forceinline__ uint32_t pack_bf2(float a, float b) {
    __nv_bfloat162 t;
    t.x = __float2bfloat16(a); t.y = __float2bfloat16(b);
    return *(uint32_t*)&t;
}

// ---------------- small kernels ----------------------------------------------
__global__ void pe_kernel(const int* __restrict__ idx) {
    int b = threadIdx.x;
    if (b < B) {
        int pe = 0;
        for (int s = 0; s < T; s++)
            if (idx[b * T + s] == PHYS_TOK) { pe = s + 1; break; }
        g_pe[b] = pe;
    }
}

__global__ void embed_kernel(const int* __restrict__ idx, const float* __restrict__ vis,
                             const float* __restrict__ wte, const float* __restrict__ wpe) {
    int i = blockIdx.x * blockDim.x + threadIdx.x;
    int d = i & (D - 1);
    int p = (i / D) & (S - 1);
    int b = i / (D * S);
    int pe = g_pe[b];
    float v;
    if (p >= pe && p < pe + KV) {
        v = vis[((size_t)b * KV + (p - pe)) * D + d];
    } else {
        int ti = (p < pe) ? p : (p - KV);
        ti = min(max(ti, 0), T - 1);
        v = wte[(size_t)idx[b * T + ti] * D + d];
    }
    g_x[i] = v + wpe[(size_t)p * D + d];
}

// LayerNorm with fused fp16 hi/lo split output
__global__ void ln_split_kernel(const float* __restrict__ in,
                                const float* __restrict__ w, const float* __restrict__ b,
                                __half* __restrict__ oh, __half* __restrict__ ol) {
    int row = blockIdx.x;
    const float* x = in + (size_t)row * D;
    float v[4]; float s = 0.f, s2 = 0.f;
#pragma unroll
    for (int u = 0; u < 4; u++) { v[u] = x[threadIdx.x + u * 256]; s += v[u]; s2 += v[u] * v[u]; }
#pragma unroll
    for (int o = 16; o; o >>= 1) { s += __shfl_xor_sync(~0u, s, o); s2 += __shfl_xor_sync(~0u, s2, o); }
    __shared__ float sh1[8], sh2[8];
    int wid = threadIdx.x >> 5, lid = threadIdx.x & 31;
    if (lid == 0) { sh1[wid] = s; sh2[wid] = s2; }
    __syncthreads();
    s = 0.f; s2 = 0.f;
#pragma unroll
    for (int wg = 0; wg < 8; wg++) { s += sh1[wg]; s2 += sh2[wg]; }
    float mean = s * (1.f / D);
    float var  = s2 * (1.f / D) - mean * mean;
    float inv  = rsqrtf(var + 1e-5f);
#pragma unroll
    for (int u = 0; u < 4; u++) {
        int j = threadIdx.x + u * 256;
        float y = (v[u] - mean) * inv * w[j] + b[j];
        __half h = __float2half_rn(y);
        oh[(size_t)row * D + j] = h;
        ol[(size_t)row * D + j] = __float2half_rn(y - __half2float(h));
    }
}

// fp32 -> single fp16 (weights)
__global__ void cvt_kernel(const float4* __restrict__ x, __half2* __restrict__ o, int n4) {
    int i = blockIdx.x * blockDim.x + threadIdx.x;
    if (i >= n4) return;
    float4 v = x[i];
    __half2 h0, h1;
    h0.x = __float2half_rn(v.x); h0.y = __float2half_rn(v.y);
    h1.x = __float2half_rn(v.z); h1.y = __float2half_rn(v.w);
    o[i * 2]     = h0;
    o[i * 2 + 1] = h1;
}

__device__ __forceinline__ float gelu_exact(float x) {
    return 0.5f * x * (1.f + erff(x * 0.70710678118654752f));
}

// ================= fp16 2-term GEMM (split A, single W) ======================
// C[M,N] = (A1+A0)[M,K] @ W[N,K]^T  (fp16, fp32 accum)
// 128x128 CTA tile, BK=32, 256 threads (8 warps 4x2), warp tile 32x64.
constexpr int LDSROW = 40;                    // 32 + 8 pad (fp16 elems)
constexpr int TILE_BYTES = 128 * LDSROW * 2;  // 10240
constexpr int BUF_BYTES  = 3 * TILE_BYTES;    // 30720 (A1, A0, W)
constexpr int GEMM_SMEM  = 2 * BUF_BYTES;     // 61440

__device__ __forceinline__ void cp_tile(uint32_t dst, const __half* __restrict__ src,
                                        int Kd, int k0) {
    int tid = threadIdx.x;
#pragma unroll
    for (int i = 0; i < 2; i++) {
        int v = tid * 2 + i;
        int row = v >> 2, seg = v & 3;
        cp16(dst + (uint32_t)(row * LDSROW + seg * 8) * 2,
             src + (size_t)row * Kd + k0 + seg * 8);
    }
}

template<bool BIAS, bool GELU, bool RES, bool SPLIT>
__global__ __launch_bounds__(256, 2)
void gemm_mma(const __half* __restrict__ A1, const __half* __restrict__ A0,
              const __half* __restrict__ W,
              const float* __restrict__ bias, const float* __restrict__ res,
              float* __restrict__ C, __half* __restrict__ Ch,
              __half* __restrict__ Cl, int N, int Kd) {
    extern __shared__ char smem[];
    const uint32_t sbase = smem_to_u32(smem);

    const int tid  = threadIdx.x;
    const int lane = tid & 31;
    const int wid  = tid >> 5;
    const int wm   = wid >> 1;
    const int wn   = wid & 1;
    const int bm   = blockIdx.x * 128;
    const int bn   = blockIdx.y * 128;

    const __half* pA1 = A1 + (size_t)bm * Kd;
    const __half* pA0 = A0 + (size_t)bm * Kd;
    const __half* pW  = W  + (size_t)bn * Kd;

    const uint32_t frag_lane = (uint32_t)((lane & 15) * LDSROW + (lane >> 4) * 8);
    const int nch = Kd / 32;

    auto issue = [&](int ch) {
        uint32_t b = sbase + (uint32_t)(ch & 1) * BUF_BYTES;
        int k0 = ch * 32;
        cp_tile(b,                  pA1, Kd, k0);
        cp_tile(b + TILE_BYTES,     pA0, Kd, k0);
        cp_tile(b + 2 * TILE_BYTES, pW,  Kd, k0);
        cp_commit();
    };

    float c[2][8][4];
#pragma unroll
    for (int mt = 0; mt < 2; mt++)
#pragma unroll
        for (int nt = 0; nt < 8; nt++)
#pragma unroll
            for (int q = 0; q < 4; q++) c[mt][nt][q] = 0.f;

    issue(0);
    if (nch > 1) issue(1);

    for (int ch = 0; ch < nch; ch++) {
        if (ch < nch - 1) cp_wait<1>(); else cp_wait<0>();
        __syncthreads();
        uint32_t b = sbase + (uint32_t)(ch & 1) * BUF_BYTES;
#pragma unroll
        for (int ks = 0; ks < 2; ks++) {
            uint32_t a1f[2][4], a0f[2][4];
#pragma unroll
            for (int mt = 0; mt < 2; mt++) {
                uint32_t off = ((uint32_t)((wm * 32 + mt * 16) * LDSROW + ks * 16) + frag_lane) * 2;
                ldmx4(a1f[mt], b + off);
                ldmx4(a0f[mt], b + TILE_BYTES + off);
            }
            uint32_t wf[8][2];
#pragma unroll
            for (int jj = 0; jj < 4; jj++) {
                uint32_t off = ((uint32_t)((wn * 64 + jj * 16) * LDSROW + ks * 16) + frag_lane) * 2;
                uint32_t t[4];
                ldmx4(t, b + 2 * TILE_BYTES + off);
                wf[jj * 2][0]     = t[0]; wf[jj * 2 + 1][0] = t[1];
                wf[jj * 2][1]     = t[2]; wf[jj * 2 + 1][1] = t[3];
            }
#pragma unroll
            for (int mt = 0; mt < 2; mt++)
#pragma unroll
                for (int nt = 0; nt < 8; nt++) {
                    mma_fp16(c[mt][nt], a1f[mt], wf[nt]);
                    mma_fp16(c[mt][nt], a0f[mt], wf[nt]);
                }
        }
        __syncthreads();
        if (ch + 2 < nch) issue(ch + 2);
    }

    // epilogue: m16n8 frag: e0,e1 -> (row=l>>2, col=(l&3)*2+{0,1}); e2,e3 -> row+8
    const int row0 = bm + wm * 32;
    const int col0 = bn + wn * 64;
#pragma unroll
    for (int mt = 0; mt < 2; mt++) {
#pragma unroll
        for (int nt = 0; nt < 8; nt++) {
            int r  = row0 + mt * 16 + (lane >> 2);
            int cl = col0 + nt * 8 + (lane & 3) * 2;
#pragma unroll
            for (int half = 0; half < 2; half++) {
                int rr = r + half * 8;
                float v0 = c[mt][nt][half * 2];
                float v1 = c[mt][nt][half * 2 + 1];
                if (BIAS) { v0 += bias[cl]; v1 += bias[cl + 1]; }
                if (GELU) { v0 = gelu_exact(v0); v1 = gelu_exact(v1); }
                if (RES) {
                    const float* rp = res + (size_t)rr * N + cl;
                    v0 += rp[0]; v1 += rp[1];
                }
                if (SPLIT) {
                    __half2 hh, ll;
                    hh.x = __float2half_rn(v0);
                    hh.y = __float2half_rn(v1);
                    ll.x = __float2half_rn(v0 - __half2float(hh.x));
                    ll.y = __float2half_rn(v1 - __half2float(hh.y));
                    *(__half2*)(Ch + (size_t)rr * N + cl) = hh;
                    *(__half2*)(Cl + (size_t)rr * N + cl) = ll;
                } else {
                    *(float2*)(C + (size_t)rr * N + cl) = make_float2(v0, v1);
                }
            }
        }
    }
}

// ================= fused flash attention (split-bf16 mma, 3-term) ============
// grid (S/128, B*H), 256 threads (8 warps x 16 q-rows). K-tile = 64 keys.
constexpr int QROW = 72;   // 64 + 8 pad
constexpr int FLASH_SMEM = (128 * QROW * 2 + 4 * 64 * QROW) * 2;

__global__ __launch_bounds__(256, 1)
void flash_kernel(const float* __restrict__ qkv,
                  __half* __restrict__ oh, __half* __restrict__ ol) {
    extern __shared__ char smem[];
    __nv_bfloat16* sQh = (__nv_bfloat16*)smem;
    __nv_bfloat16* sQl = sQh + 128 * QROW;
    __nv_bfloat16* sKh = sQl + 128 * QROW;
    __nv_bfloat16* sKl = sKh + 64 * QROW;
    __nv_bfloat16* sVh = sKl + 64 * QROW;
    __nv_bfloat16* sVl = sVh + 64 * QROW;

    const int tid = threadIdx.x, lane = tid & 31, w = tid >> 5;
    const int bh = blockIdx.y, b = bh >> 4, h = bh & 15;
    const int qBase = blockIdx.x * 128;
    const int pe = g_pe[b], ve = pe + KV;

    for (int i = tid; i < 2048; i += 256) {
        int row = i >> 4, col = (i & 15) * 4;
        float4 q4 = *(const float4*)(qkv + (size_t)(b * S + qBase + row) * (3 * D) + h * DH + col);
        int o = row * QROW + col;
        float f[4] = { q4.x, q4.y, q4.z, q4.w };
#pragma unroll
        for (int u = 0; u < 4; u++) {
            __nv_bfloat16 hh = __float2bfloat16(f[u]);
            sQh[o + u] = hh;
            sQl[o + u] = __float2bfloat16(f[u] - __bfloat162float(hh));
        }
    }
    __syncthreads();

    const uint32_t aQh = smem_to_u32(sQh), aQl = smem_to_u32(sQl);
    const uint32_t aKh = smem_to_u32(sKh), aKl = smem_to_u32(sKl);
    const uint32_t aVh = smem_to_u32(sVh), aVl = smem_to_u32(sVl);
    const uint32_t flq = (uint32_t)((lane & 15) * QROW + (lane >> 4) * 8);
    uint32_t qh[4][4], ql[4][4];
#pragma unroll
    for (int kk = 0; kk < 4; kk++) {
        uint32_t off = ((uint32_t)(w * 16 * QROW + kk * 16) + flq) * 2;
        ldmx4(qh[kk], aQh + off);
        ldmx4(ql[kk], aQl + off);
    }

    float acc[8][4];
#pragma unroll
    for (int nt = 0; nt < 8; nt++)
#pragma unroll
        for (int e = 0; e < 4; e++) acc[nt][e] = 0.f;
    float m0 = -1e30f, m1 = -1e30f, l0 = 0.f, l1 = 0.f;

    const int qr = qBase + w * 16 + (lane >> 2);
    const int kEnd = min(S, max(qBase + 128, ve));

    for (int k0 = 0; k0 < kEnd; k0 += 64) {
        __syncthreads();
        for (int i = tid; i < 1024; i += 256) {
            int row = i >> 4, col = (i & 15) * 4;
            const float* base = qkv + (size_t)(b * S + k0 + row) * (3 * D) + h * DH + col;
            float4 k4 = *(const float4*)(base + D);
            float4 v4 = *(const float4*)(base + 2 * D);
            int o = row * QROW + col;
            float fk[4] = { k4.x, k4.y, k4.z, k4.w };
            float fv[4] = { v4.x, v4.y, v4.z, v4.w };
#pragma unroll
            for (int u = 0; u < 4; u++) {
                __nv_bfloat16 hk = __float2bfloat16(fk[u]);
                sKh[o + u] = hk;
                sKl[o + u] = __float2bfloat16(fk[u] - __bfloat162float(hk));
                __nv_bfloat16 hv = __float2bfloat16(fv[u]);
                sVh[o + u] = hv;
                sVl[o + u] = __float2bfloat16(fv[u] - __bfloat162float(hv));
            }
        }
        __syncthreads();

        float c[8][4];
#pragma unroll
        for (int nt = 0; nt < 8; nt++)
#pragma unroll
            for (int e = 0; e < 4; e++) c[nt][e] = 0.f;
#pragma unroll
        for (int kk = 0; kk < 4; kk++) {
#pragma unroll
            for (int jj = 0; jj < 4; jj++) {
                uint32_t off = ((uint32_t)((jj * 16) * QROW + kk * 16) + flq) * 2;
                uint32_t th[4], tl[4];
                ldmx4(th, aKh + off);
                ldmx4(tl, aKl + off);
                uint32_t bh0[2] = { th[0], th[2] }, bh1[2] = { th[1], th[3] };
                uint32_t bl0[2] = { tl[0], tl[2] }, bl1[2] = { tl[1], tl[3] };
                mma_bf16(c[jj * 2],     qh[kk], bh0);
                mma_bf16(c[jj * 2],     qh[kk], bl0);
                mma_bf16(c[jj * 2],     ql[kk], bh0);
                mma_bf16(c[jj * 2 + 1], qh[kk], bh1);
                mma_bf16(c[jj * 2 + 1], qh[kk], bl1);
                mma_bf16(c[jj * 2 + 1], ql[kk], bh1);
            }
        }

        float mx0 = -1e30f, mx1 = -1e30f;
#pragma unroll
        for (int nt = 0; nt < 8; nt++) {
            int kc = k0 + nt * 8 + (lane & 3) * 2;
#pragma unroll
            for (int e = 0; e < 4; e++) {
                int q = qr + ((e >= 2) ? 8 : 0);
                int k = kc + (e & 1);
                bool allowed = (q < pe && k < pe) ||
                               (q >= pe && q < ve && k < ve) ||
                               (q >= ve && k <= q);
                float s = allowed ? c[nt][e] * 0.125f : -1e9f;
                c[nt][e] = s;
                if (e < 2) mx0 = fmaxf(mx0, s); else mx1 = fmaxf(mx1, s);
            }
        }
        mx0 = fmaxf(mx0, __shfl_xor_sync(~0u, mx0, 1));
        mx0 = fmaxf(mx0, __shfl_xor_sync(~0u, mx0, 2));
        mx1 = fmaxf(mx1, __shfl_xor_sync(~0u, mx1, 1));
        mx1 = fmaxf(mx1, __shfl_xor_sync(~0u, mx1, 2));

        float mn0 = fmaxf(m0, mx0), mn1 = fmaxf(m1, mx1);
        float al0 = __expf(m0 - mn0), al1 = __expf(m1 - mn1);
        m0 = mn0; m1 = mn1;

        uint32_t ph[4][4], pl[4][4];
        float rs0 = 0.f, rs1 = 0.f;
#pragma unroll
        for (int nt = 0; nt < 8; nt++) {
            float p0 = __expf(c[nt][0] - m0);
            float p1 = __expf(c[nt][1] - m0);
            float p2 = __expf(c[nt][2] - m1);
            float p3 = __expf(c[nt][3] - m1);
            rs0 += p0 + p1; rs1 += p2 + p3;
            __nv_bfloat16 h0 = __float2bfloat16(p0), h1 = __float2bfloat16(p1);
            __nv_bfloat16 h2 = __float2bfloat16(p2), h3 = __float2bfloat16(p3);
            int ck = nt >> 1, ps = (nt & 1) * 2;
            __nv_bfloat162 t;
            t.x = h0; t.y = h1; ph[ck][ps]     = *(uint32_t*)&t;
            t.x = h2; t.y = h3; ph[ck][ps + 1] = *(uint32_t*)&t;
            pl[ck][ps]     = pack_bf2(p0 - __bfloat162float(h0), p1 - __bfloat162float(h1));
            pl[ck][ps + 1] = pack_bf2(p2 - __bfloat162float(h2), p3 - __bfloat162float(h3));
        }
        rs0 += __shfl_xor_sync(~0u, rs0, 1); rs0 += __shfl_xor_sync(~0u, rs0, 2);
        rs1 += __shfl_xor_sync(~0u, rs1, 1); rs1 += __shfl_xor_sync(~0u, rs1, 2);
        l0 = l0 * al0 + rs0;
        l1 = l1 * al1 + rs1;

#pragma unroll
        for (int nt = 0; nt < 8; nt++) {
            acc[nt][0] *= al0; acc[nt][1] *= al0;
            acc[nt][2] *= al1; acc[nt][3] *= al1;
        }

        const uint32_t flv = (uint32_t)(((lane & 7) + ((lane >> 3) & 1) * 8) * QROW + (lane >> 4) * 8);
#pragma unroll
        for (int kk = 0; kk < 4; kk++) {
#pragma unroll
            for (int jj = 0; jj < 4; jj++) {
                uint32_t off = ((uint32_t)(kk * 16 * QROW + jj * 16) + flv) * 2;
                uint32_t th[4], tl[4];
                ldmx4t(th, aVh + off);
                ldmx4t(tl, aVl + off);
                uint32_t bh0[2] = { th[0], th[1] }, bh1[2] = { th[2], th[3] };
                uint32_t bl0[2] = { tl[0], tl[1] }, bl1[2] = { tl[2], tl[3] };
                mma_bf16(acc[jj * 2],     ph[kk], bh0);
                mma_bf16(acc[jj * 2],     ph[kk], bl0);
                mma_bf16(acc[jj * 2],     pl[kk], bh0);
                mma_bf16(acc[jj * 2 + 1], ph[kk], bh1);
                mma_bf16(acc[jj * 2 + 1], ph[kk], bl1);
                mma_bf16(acc[jj * 2 + 1], pl[kk], bh1);
            }
        }
    }

    // ---- normalize + fp16 split write ----
    const float il0 = 1.f / l0, il1 = 1.f / l1;
#pragma unroll
    for (int nt = 0; nt < 8; nt++) {
        int dcol = h * DH + nt * 8 + (lane & 3) * 2;
        size_t o0 = (size_t)(b * S + qr) * D + dcol;
        size_t o1 = (size_t)(b * S + qr + 8) * D + dcol;
        float v0 = acc[nt][0] * il0, v1 = acc[nt][1] * il0;
        float v2 = acc[nt][2] * il1, v3 = acc[nt][3] * il1;
        __half2 hh, ll;
        hh.x = __float2half_rn(v0); hh.y = __float2half_rn(v1);
        ll.x = __float2half_rn(v0 - __half2float(hh.x));
        ll.y = __float2half_rn(v1 - __half2float(hh.y));
        *(__half2*)(oh + o0) = hh;
        *(__half2*)(ol + o0) = ll;
        hh.x = __float2half_rn(v2); hh.y = __float2half_rn(v3);
        ll.x = __float2half_rn(v2 - __half2float(hh.x));
        ll.y = __float2half_rn(v3 - __half2float(hh.y));
        *(__half2*)(oh + o1) = hh;
        *(__half2*)(ol + o1) = ll;
    }
}

// ---------------- host: launch sequence --------------------------------------
static inline void cvt(const float* x, __half* o, size_t n) {
    int n4 = (int)(n / 4);
    cvt_kernel<<<(n4 + 255) / 256, 256>>>((const float4*)x, (__half2*)o, n4);
}

extern "C" void kernel_launch(void* const* d_in, const int* in_sizes, int n_in,
                              void* d_out, int out_size) {
    const int*   idx    = (const int*)  d_in[0];
    const float* vis    = (const float*)d_in[1];
    const float* wte    = (const float*)d_in[2];
    const float* wpe    = (const float*)d_in[3];
    const float* qkv_w  = (const float*)d_in[4];
    const float* qkv_b  = (const float*)d_in[5];
    const float* out_w  = (const float*)d_in[6];
    const float* out_b  = (const float*)d_in[7];
    const float* ln1_w  = (const float*)d_in[8];
    const float* ln1_b  = (const float*)d_in[9];
    const float* ln2_w  = (const float*)d_in[10];
    const float* ln2_b  = (const float*)d_in[11];
    const float* ff1_w  = (const float*)d_in[12];
    const float* ff1_b  = (const float*)d_in[13];
    const float* ff2_w  = (const float*)d_in[14];
    const float* ff2_b  = (const float*)d_in[15];
    const float* lnf_w  = (const float*)d_in[16];
    const float* lnf_b  = (const float*)d_in[17];
    float* logits = (float*)d_out;

    cudaFuncSetAttribute(gemm_mma<true,  false, false, false>, cudaFuncAttributeMaxDynamicSharedMemorySize, GEMM_SMEM);
    cudaFuncSetAttribute(gemm_mma<true,  false, true,  false>, cudaFuncAttributeMaxDynamicSharedMemorySize, GEMM_SMEM);
    cudaFuncSetAttribute(gemm_mma<true,  true,  false, true >, cudaFuncAttributeMaxDynamicSharedMemorySize, GEMM_SMEM);
    cudaFuncSetAttribute(gemm_mma<false, false, false, false>, cudaFuncAttributeMaxDynamicSharedMemorySize, GEMM_SMEM);
    cudaFuncSetAttribute(flash_kernel, cudaFuncAttributeMaxDynamicSharedMemorySize, FLASH_SMEM);

    float *px, *pqkv;
    cudaGetSymbolAddress((void**)&px,   g_x);
    cudaGetSymbolAddress((void**)&pqkv, g_qkv);
    __half *pah, *pal, *pa2h, *pa2l, *pwq, *pwo, *pf1, *pf2, *pte;
    cudaGetSymbolAddress((void**)&pah,  a_h);
    cudaGetSymbolAddress((void**)&pal,  a_l);
    cudaGetSymbolAddress((void**)&pa2h, a2_h);
    cudaGetSymbolAddress((void**)&pa2l, a2_l);
    cudaGetSymbolAddress((void**)&pwq,  w_qkv);
    cudaGetSymbolAddress((void**)&pwo,  w_out);
    cudaGetSymbolAddress((void**)&pf1,  w_ff1);
    cudaGetSymbolAddress((void**)&pf2,  w_ff2);
    cudaGetSymbolAddress((void**)&pte,  w_te);

    // weight conversions (fp32 -> fp16) — must run every call (determinism)
    cvt(qkv_w, pwq, (size_t)L * 3 * D * D);
    cvt(out_w, pwo, (size_t)L * D * D);
    cvt(ff1_w, pf1, (size_t)L * 4 * D * D);
    cvt(ff2_w, pf2, (size_t)L * 4 * D * D);
    cvt(wte,   pte, (size_t)V * D);

    pe_kernel<<<1, 32>>>(idx);
    embed_kernel<<<(NTOK * D) / 256, 256>>>(idx, vis, wte, wpe);

    for (int l = 0; l < L; l++) {
        const __half* qw  = pwq + (size_t)l * 3 * D * D;
        const __half* ow  = pwo + (size_t)l * D * D;
        const __half* f1w = pf1 + (size_t)l * 4 * D * D;
        const __half* f2w = pf2 + (size_t)l * 4 * D * D;
        const float* qb  = qkv_b + (size_t)l * 3 * D;
        const float* ob  = out_b + (size_t)l * D;
        const float* f1b = ff1_b + (size_t)l * 4 * D;
        const float* f2b = ff2_b + (size_t)l * D;

        ln_split_kernel<<<NTOK, 256>>>(px, ln1_w + l * D, ln1_b + l * D, pah, pal);
        gemm_mma<true, false, false, false><<<dim3(NTOK / 128, 3 * D / 128), 256, GEMM_SMEM>>>(
            pah, pal, qw, qb, nullptr, pqkv, nullptr, nullptr, 3 * D, D);

        flash_kernel<<<dim3(S / 128, B * H), 256, FLASH_SMEM>>>(pqkv, pah, pal);

        gemm_mma<true, false, true, false><<<dim3(NTOK / 128, D / 128), 256, GEMM_SMEM>>>(
            pah, pal, ow, ob, px, px, nullptr, nullptr, D, D);

        ln_split_kernel<<<NTOK, 256>>>(px, ln2_w + l * D, ln2_b + l * D, pah, pal);
        gemm_mma<true, true, false, true><<<dim3(NTOK / 128, 4 * D / 128), 256, GEMM_SMEM>>>(
            pah, pal, f1w, f1b, nullptr, nullptr, pa2h, pa2l, 4 * D, D);

        gemm_mma<true, false, true, false><<<dim3(NTOK / 128, D / 128), 256, GEMM_SMEM>>>(
            pa2h, pa2l, f2w, f2b, px, px, nullptr, nullptr, D, 4 * D);
    }

    ln_split_kernel<<<NTOK, 256>>>(px, lnf_w, lnf_b, pah, pal);
    gemm_mma<false, false, false, false><<<dim3(NTOK / 128, V / 128), 256, GEMM_SMEM>>>(
        pah, pal, pte, nullptr, nullptr, logits, nullptr, nullptr, V, D);
}